// round 4
// baseline (speedup 1.0000x reference)
#include <cuda_runtime.h>

// DifferentiableSMMPC: u_traj starts at 0 and the update k = -Q_uu_inv @ (2R*u)
// is identically 0 when u == 0, so u never leaves 0. Output u_traj[:, 0] is a
// (2048, 128) fp32 zero array -> pure 1 MiB zero store. Launch-overhead bound;
// minimize CTA count and per-thread SASS.

// Exact-fit path: one float4 per thread, no bounds check.
__global__ void __launch_bounds__(1024) smmpc_zero_fill_exact(float4* __restrict__ out) {
    out[blockIdx.x * 1024u + threadIdx.x] = make_float4(0.f, 0.f, 0.f, 0.f);
}

// Guarded fallback (handles any out_size; scalar floats).
__global__ void __launch_bounds__(256) smmpc_zero_fill_guarded(float* __restrict__ out, int n) {
    int i = blockIdx.x * blockDim.x + threadIdx.x;
    if (i < n) out[i] = 0.0f;
}

extern "C" void kernel_launch(void* const* d_in, const int* in_sizes, int n_in,
                              void* d_out, int out_size) {
    (void)d_in; (void)in_sizes; (void)n_in;
    // Expected out_size = 2048*128 = 262144 fp32 = 65536 float4 = 64 blocks x 1024 thr.
    if ((out_size & 3) == 0 && (out_size / 4) % 1024 == 0) {
        int blocks = (out_size / 4) / 1024;  // 64 for the expected shape
        smmpc_zero_fill_exact<<<blocks, 1024>>>(reinterpret_cast<float4*>(d_out));
    } else {
        int threads = 256;
        int blocks = (out_size + threads - 1) / threads;
        smmpc_zero_fill_guarded<<<blocks, threads>>>(reinterpret_cast<float*>(d_out), out_size);
    }
}

// round 5
// speedup vs baseline: 1.0764x; 1.0764x over previous
#include <cuda_runtime.h>

// DifferentiableSMMPC: u starts at 0, update k = -Q_uu_inv @ (2R*u) is 0 when
// u==0, so output u_traj[:,0] is a (2048,128) fp32 zero array. Pure 1 MiB zero
// store; launch-overhead bound. Minimize thread ramp (16K threads) and store
// issue count (256-bit STG, sm_100+).

__global__ void __launch_bounds__(256) smmpc_zero_fill_v8(float* __restrict__ out) {
    // 64 CTAs x 256 threads; each thread writes 2 x 32B = 64B.
    // Coalesced: consecutive threads hit consecutive 32B chunks.
    unsigned t = blockIdx.x * 256u + threadIdx.x;          // 0..16383
    float* p0 = out + (unsigned long long)t * 8u;           // first 32B chunk
    float* p1 = out + (16384ull + t) * 8u;                  // second half of buffer
    asm volatile(
        "st.global.v8.f32 [%0], {%2, %2, %2, %2, %2, %2, %2, %2};\n\t"
        "st.global.v8.f32 [%1], {%2, %2, %2, %2, %2, %2, %2, %2};\n\t"
        :: "l"(p0), "l"(p1), "f"(0.0f) : "memory");
}

// Guarded generic fallback (any out_size).
__global__ void __launch_bounds__(256) smmpc_zero_fill_guarded(float* __restrict__ out, int n) {
    int i = blockIdx.x * blockDim.x + threadIdx.x;
    if (i < n) out[i] = 0.0f;
}

extern "C" void kernel_launch(void* const* d_in, const int* in_sizes, int n_in,
                              void* d_out, int out_size) {
    (void)d_in; (void)in_sizes; (void)n_in;
    // Expected out_size = 2048*128 = 262144 fp32 = 1 MiB = 32768 x 32B chunks.
    if (out_size == 262144) {
        smmpc_zero_fill_v8<<<64, 256>>>(reinterpret_cast<float*>(d_out));
    } else {
        int threads = 256;
        int blocks = (out_size + threads - 1) / threads;
        smmpc_zero_fill_guarded<<<blocks, threads>>>(reinterpret_cast<float*>(d_out), out_size);
    }
}